// round 14
// baseline (speedup 1.0000x reference)
#include <cuda_runtime.h>
#include <cuda_fp16.h>
#include <cstdint>
#include <cstring>

#define DEVINL __device__ __forceinline__

// ---------------- problem sizes ----------------
constexpr int M_TOK = 8192;        // B*S
constexpr int DIM   = 2048;        // D
constexpr int NEXP  = 64;
constexpr int N1 = 4096;           // E*R   (gemm1 N == gemm2 K)
constexpr int K1 = DIM;            // 2048
constexpr int N2 = DIM;            // 2048
constexpr int K2 = N1;             // 4096

// ---------------- tiling ----------------
constexpr int TM = 128, KC = 64, STAGES = 3;
constexpr int A_TILE = TM * KC * 2;            // 16 KB
constexpr int NTHREADS = 128;                  // 4 warps

// ---------------- device scratch (fp16 operands) ----------------
__device__ __align__(16) __half g_x [M_TOK * K1];
__device__ __align__(16) __half g_wu[N1 * K1];
__device__ __align__(16) __half g_wd[N2 * K2];
__device__ __align__(16) __half g_h [M_TOK * K2];

// ---------------- helpers ----------------
DEVINL uint32_t smem_u32(const void* p) {
    uint32_t r;
    asm("{ .reg .u64 t; cvta.to.shared.u64 t, %1; cvt.u32.u64 %0, t; }"
        : "=r"(r) : "l"(p));
    return r;
}

DEVINL void cp16(uint32_t dst, const void* src) {
    asm volatile("cp.async.cg.shared.global [%0], [%1], 16;"
                 :: "r"(dst), "l"(src) : "memory");
}
DEVINL void cp_commit() { asm volatile("cp.async.commit_group;" ::: "memory"); }
template <int N> DEVINL void cp_wait() {
    asm volatile("cp.async.wait_group %0;" :: "n"(N) : "memory");
}

DEVINL void ldsm4(uint32_t (&r)[4], uint32_t addr) {
    asm volatile("ldmatrix.sync.aligned.m8n8.x4.shared.b16 {%0,%1,%2,%3}, [%4];"
                 : "=r"(r[0]), "=r"(r[1]), "=r"(r[2]), "=r"(r[3]) : "r"(addr));
}

DEVINL void mma16816(float (&c)[4], const uint32_t (&a)[4], const uint32_t* b) {
    asm volatile(
        "mma.sync.aligned.m16n8k16.row.col.f32.f16.f16.f32 "
        "{%0,%1,%2,%3}, {%4,%5,%6,%7}, {%8,%9}, {%0,%1,%2,%3};"
        : "+f"(c[0]), "+f"(c[1]), "+f"(c[2]), "+f"(c[3])
        : "r"(a[0]), "r"(a[1]), "r"(a[2]), "r"(a[3]), "r"(b[0]), "r"(b[1]));
}

DEVINL uint32_t pk2h(__half a, __half b) {
    __half2 t = __halves2half2(a, b);
    uint32_t u;
    memcpy(&u, &t, 4);
    return u;
}

// ---------------- convert: fp32 -> fp16 ----------------
DEVINL void cvt4(float4 v, __half* dst, int i) {
    uint2 u;
    u.x = pk2h(__float2half_rn(v.x), __float2half_rn(v.y));
    u.y = pk2h(__float2half_rn(v.z), __float2half_rn(v.w));
    reinterpret_cast<uint2*>(dst)[i] = u;
}

__global__ void convert_kernel(const float4* __restrict__ x,
                               const float4* __restrict__ wu,
                               const float4* __restrict__ wd) {
    const int X4  = M_TOK * K1 / 4;
    const int WU4 = N1 * K1 / 4;
    const int WD4 = N2 * K2 / 4;
    const int stride = gridDim.x * blockDim.x;
    const int t0 = blockIdx.x * blockDim.x + threadIdx.x;
    for (int i = t0; i < X4;  i += stride) cvt4(x[i],  g_x,  i);
    for (int i = t0; i < WU4; i += stride) cvt4(wu[i], g_wu, i);
    for (int i = t0; i < WD4; i += stride) cvt4(wd[i], g_wd, i);
}

// ---------------- tile loader (SW128 swizzle) ----------------
template <int ROWS>
DEVINL void load_tile(uint32_t sub, const __half* __restrict__ src,
                      int row0, int k0, int KDIM, int tid) {
    constexpr int ITERS = ROWS * 8 / NTHREADS;
#pragma unroll
    for (int j = 0; j < ITERS; j++) {
        const int idx = tid + j * NTHREADS;
        const int rr = idx >> 3;
        const int ss = idx & 7;
        const uint32_t off = (uint32_t)(rr * 128 + ss * 16);
        const uint32_t dst = sub + (off ^ ((off >> 3) & 0x70));
        cp16(dst, src + (size_t)(row0 + rr) * KDIM + (k0 + ss * 8));
    }
}

template <int TNL>
DEVINL void load_chunk(uint32_t sb, int k0, int tid,
                       const __half* A, const __half* B,
                       int m0, int n0, int KDIM) {
    load_tile<TM>(sb,           A, m0, k0, KDIM, tid);
    load_tile<TNL>(sb + A_TILE, B, n0, k0, KDIM, tid);
    cp_commit();
}

// ---------------- fragment loads ----------------
DEVINL void load_a_frags(uint32_t subA, int ks, int lane, int wm,
                         uint32_t (&a)[4][4]) {
    const int a_r0 = wm * 64 + (lane & 7) + ((lane >> 3) & 1) * 8;
    const int a_k8 = (lane >> 4);
#pragma unroll
    for (int mb = 0; mb < 4; mb++) {
        const int r = a_r0 + mb * 16;
        const int kk = ks * 16 + a_k8 * 8;
        const uint32_t off = (uint32_t)(r * 128) + (((uint32_t)(kk * 2)) ^ (uint32_t)((r & 7) << 4));
        ldsm4(a[mb], subA + off);
    }
}

template <int GN>
DEVINL void load_b_frag(uint32_t subB, int ks, int g, int lane, int wn,
                        uint32_t (&b)[4]) {
    const int b_r0 = wn * (GN * 16) + (lane & 7) + (lane >> 4) * 8;
    const int b_k8 = (lane >> 3) & 1;
    const int r = b_r0 + g * 16;
    const int kk = ks * 16 + b_k8 * 8;
    const uint32_t off = (uint32_t)(r * 128) + (((uint32_t)(kk * 2)) ^ (uint32_t)((r & 7) << 4));
    ldsm4(b, subB + off);
}

// ---------------- GEMM body ----------------
// MODE 1: X * WupT, fused silu*mask -> h (fp16).  TN=128.
// MODE 2: h * WdnT -> out fp32.                   TN=64, PDL: B loads pre-sync.
template <int MODE>
__global__ void __launch_bounds__(NTHREADS, 2)
gemm_kernel(const float* __restrict__ mask, float* __restrict__ out) {
    constexpr int KDIM = (MODE == 1) ? K1 : K2;
    constexpr int NC = KDIM / KC;
    constexpr int TNL = (MODE == 1) ? 128 : 64;
    constexpr int GN = TNL / 32;                   // B 16-col groups per warp
    constexpr int B_TILE_L = TNL * KC * 2;
    constexpr int STAGE_L = A_TILE + B_TILE_L;
    const __half* A = (MODE == 1) ? g_x  : g_h;
    const __half* B = (MODE == 1) ? g_wu : g_wd;

    extern __shared__ __align__(1024) uint8_t smem_raw[];
    const uint32_t base = (smem_u32(smem_raw) + 1023u) & ~1023u;

    const int tid = threadIdx.x;
    const int lane = tid & 31;
    const int wid = tid >> 5;
    const int wm = wid >> 1;          // 0..1  (64-row half)
    const int wn = wid & 1;           // 0..1  (n half)
    const int m0 = blockIdx.y * TM;
    const int n0 = blockIdx.x * TNL;

    float acc[4][2 * GN][4];
#pragma unroll
    for (int i = 0; i < 4; i++)
#pragma unroll
        for (int j = 0; j < 2 * GN; j++)
#pragma unroll
            for (int q = 0; q < 4; q++) acc[i][j][q] = 0.f;

    // ---------------- prologue ----------------
    if (MODE == 2) {
        // PDL: B (g_wd) does not depend on GEMM1. Prefetch it before the
        // cross-kernel dependency sync; then A (g_h) after.
        load_tile<TNL>(base + A_TILE,           B, n0, 0,  KDIM, tid);
        load_tile<TNL>(base + STAGE_L + A_TILE, B, n0, KC, KDIM, tid);
        cudaGridDependencySynchronize();
        load_tile<TM>(base,           A, m0, 0,  KDIM, tid);
        cp_commit();                                // group0 = {B0, B1, A0}
        load_tile<TM>(base + STAGE_L, A, m0, KC, KDIM, tid);
        cp_commit();                                // group1 = {A1}
    } else {
        load_chunk<TNL>(base,           0,  tid, A, B, m0, n0, KDIM);
        load_chunk<TNL>(base + STAGE_L, KC, tid, A, B, m0, n0, KDIM);
    }

    for (int c = 0; c < NC; ++c) {
        if (c + 1 < NC) cp_wait<1>(); else cp_wait<0>();
        __syncthreads();   // chunk c resident; stage (c-1)%3 free

        const uint32_t sbc = base + (c % STAGES) * STAGE_L;
        const uint32_t subA = sbc;
        const uint32_t subB = sbc + A_TILE;

        // register double-buffered fragment pipeline
        uint32_t aF[2][4][4];
        uint32_t bF[2][4];
        load_a_frags(subA, 0, lane, wm, aF[0]);
        load_b_frag<GN>(subB, 0, 0, lane, wn, bF[0]);

#pragma unroll
        for (int ks = 0; ks < KC / 16; ks++) {
            // prefetch next ks's A fragments into the alternate buffer
            if (ks + 1 < KC / 16)
                load_a_frags(subA, ks + 1, lane, wm, aF[(ks + 1) & 1]);

#pragma unroll
            for (int g = 0; g < GN; g++) {
                // prefetch next B fragment: (ks, g+1) or (ks+1, 0)
                if (g + 1 < GN)
                    load_b_frag<GN>(subB, ks, g + 1, lane, wn, bF[(g + 1) & 1]);
                else if (ks + 1 < KC / 16)
                    load_b_frag<GN>(subB, ks + 1, 0, lane, wn, bF[GN & 1]);

                uint32_t (&a)[4][4] = aF[ks & 1];
                uint32_t (&b)[4]    = bF[g & 1];
#pragma unroll
                for (int h = 0; h < 2; h++)
#pragma unroll
                    for (int mb = 0; mb < 4; mb++)
                        mma16816(acc[mb][g * 2 + h], a[mb], b + 2 * h);
            }

            // cp.async burst for the next stage rides in the ks0 MMA shadow
            if (ks == 0 && c + 2 < NC)
                load_chunk<TNL>(base + ((c + 2) % STAGES) * STAGE_L, (c + 2) * KC,
                                tid, A, B, m0, n0, KDIM);
        }
    }

    // ---------------- epilogue ----------------
    const int mw0 = m0 + wm * 64;
    const int nw0 = n0 + wn * (GN * 16);
#pragma unroll
    for (int mb = 0; mb < 4; mb++) {
        const int r0 = mw0 + mb * 16 + (lane >> 2);
        if (MODE == 1) {
            const int e = nw0 >> 6;   // one expert per 64-wide warp n-tile (R=64)
            const float mk0 = mask[(size_t)r0 * NEXP + e];
            const float mk1 = mask[(size_t)(r0 + 8) * NEXP + e];
#pragma unroll
            for (int nb = 0; nb < 2 * GN; nb++) {
                const int col = nw0 + nb * 8 + (lane & 3) * 2;
                float v[4] = {acc[mb][nb][0], acc[mb][nb][1],
                              acc[mb][nb][2], acc[mb][nb][3]};
                float hv[4];
                hv[0] = v[0] * (1.f / (1.f + __expf(-v[0]))) * mk0;
                hv[1] = v[1] * (1.f / (1.f + __expf(-v[1]))) * mk0;
                hv[2] = v[2] * (1.f / (1.f + __expf(-v[2]))) * mk1;
                hv[3] = v[3] * (1.f / (1.f + __expf(-v[3]))) * mk1;
                *reinterpret_cast<uint32_t*>(g_h + (size_t)r0 * K2 + col) =
                    pk2h(__float2half_rn(hv[0]), __float2half_rn(hv[1]));
                *reinterpret_cast<uint32_t*>(g_h + (size_t)(r0 + 8) * K2 + col) =
                    pk2h(__float2half_rn(hv[2]), __float2half_rn(hv[3]));
            }
        } else {
#pragma unroll
            for (int nb = 0; nb < 2 * GN; nb++) {
                const int col = nw0 + nb * 8 + (lane & 3) * 2;
                *reinterpret_cast<float2*>(out + (size_t)r0 * N2 + col) =
                    make_float2(acc[mb][nb][0], acc[mb][nb][1]);
                *reinterpret_cast<float2*>(out + (size_t)(r0 + 8) * N2 + col) =
                    make_float2(acc[mb][nb][2], acc[mb][nb][3]);
            }
        }
    }

    if (MODE == 1) {
        // all of this block's h stores issued; let GEMM2 start launching
        cudaTriggerProgrammaticLaunchCompletion();
    }
}

// ---------------- launch ----------------
extern "C" void kernel_launch(void* const* d_in, const int* in_sizes, int n_in,
                              void* d_out, int out_size) {
    const float* x    = (const float*)d_in[0];   // [8192, 2048]
    const float* mask = (const float*)d_in[1];   // [8192, 64]
    const float* wu   = (const float*)d_in[2];   // [4096, 2048]
    const float* wd   = (const float*)d_in[3];   // [2048, 4096]
    float* out = (float*)d_out;

    constexpr int SMEM1 = STAGES * (A_TILE + 128 * KC * 2) + 1024;  // 97 KB
    constexpr int SMEM2 = STAGES * (A_TILE + 64  * KC * 2) + 1024;  // 73.5 KB

    cudaFuncSetAttribute(gemm_kernel<1>, cudaFuncAttributeMaxDynamicSharedMemorySize, SMEM1);
    cudaFuncSetAttribute(gemm_kernel<2>, cudaFuncAttributeMaxDynamicSharedMemorySize, SMEM2);

    convert_kernel<<<1024, 256>>>((const float4*)x, (const float4*)wu, (const float4*)wd);

    gemm_kernel<1><<<dim3(N1 / 128, M_TOK / TM), NTHREADS, SMEM1>>>(mask, nullptr);

    // GEMM2 with programmatic dependent launch: overlaps its launch + B
    // prefetch with GEMM1's tail wave. Data dependency on g_h is enforced by
    // cudaGridDependencySynchronize() inside the kernel.
    {
        cudaLaunchConfig_t cfg = {};
        cfg.gridDim = dim3(N2 / 64, M_TOK / TM);
        cfg.blockDim = dim3(NTHREADS, 1, 1);
        cfg.dynamicSmemBytes = SMEM2;
        cfg.stream = 0;
        cudaLaunchAttribute attrs[1];
        attrs[0].id = cudaLaunchAttributeProgrammaticStreamSerialization;
        attrs[0].val.programmaticStreamSerializationAllowed = 1;
        cfg.attrs = attrs;
        cfg.numAttrs = 1;
        cudaLaunchKernelEx(&cfg, gemm_kernel<2>, (const float*)nullptr, out);
    }
}

// round 15
// speedup vs baseline: 1.0459x; 1.0459x over previous
#include <cuda_runtime.h>
#include <cuda_fp16.h>
#include <cstdint>
#include <cstring>

#define DEVINL __device__ __forceinline__

// ---------------- problem sizes ----------------
constexpr int M_TOK = 8192;        // B*S
constexpr int DIM   = 2048;        // D
constexpr int NEXP  = 64;
constexpr int N1 = 4096;           // E*R   (gemm1 N == gemm2 K)
constexpr int K1 = DIM;            // 2048
constexpr int N2 = DIM;            // 2048
constexpr int K2 = N1;             // 4096

// ---------------- tiling ----------------
constexpr int TM = 128, KC = 64, STAGES = 3;
constexpr int A_TILE = TM * KC * 2;            // 16 KB
constexpr int NTHREADS = 128;                  // 4 warps

// ---------------- device scratch (fp16 operands) ----------------
__device__ __align__(16) __half g_x [M_TOK * K1];
__device__ __align__(16) __half g_wu[N1 * K1];
__device__ __align__(16) __half g_wd[N2 * K2];
__device__ __align__(16) __half g_h [M_TOK * K2];

// ---------------- helpers ----------------
DEVINL uint32_t smem_u32(const void* p) {
    uint32_t r;
    asm("{ .reg .u64 t; cvta.to.shared.u64 t, %1; cvt.u32.u64 %0, t; }"
        : "=r"(r) : "l"(p));
    return r;
}

DEVINL void cp16(uint32_t dst, const void* src) {
    asm volatile("cp.async.cg.shared.global [%0], [%1], 16;"
                 :: "r"(dst), "l"(src) : "memory");
}
DEVINL void cp_commit() { asm volatile("cp.async.commit_group;" ::: "memory"); }
template <int N> DEVINL void cp_wait() {
    asm volatile("cp.async.wait_group %0;" :: "n"(N) : "memory");
}

DEVINL void ldsm4(uint32_t (&r)[4], uint32_t addr) {
    asm volatile("ldmatrix.sync.aligned.m8n8.x4.shared.b16 {%0,%1,%2,%3}, [%4];"
                 : "=r"(r[0]), "=r"(r[1]), "=r"(r[2]), "=r"(r[3]) : "r"(addr));
}

DEVINL void mma16816(float (&c)[4], const uint32_t (&a)[4], const uint32_t* b) {
    asm volatile(
        "mma.sync.aligned.m16n8k16.row.col.f32.f16.f16.f32 "
        "{%0,%1,%2,%3}, {%4,%5,%6,%7}, {%8,%9}, {%0,%1,%2,%3};"
        : "+f"(c[0]), "+f"(c[1]), "+f"(c[2]), "+f"(c[3])
        : "r"(a[0]), "r"(a[1]), "r"(a[2]), "r"(a[3]), "r"(b[0]), "r"(b[1]));
}

DEVINL uint32_t pk2h(__half a, __half b) {
    __half2 t = __halves2half2(a, b);
    uint32_t u;
    memcpy(&u, &t, 4);
    return u;
}

// ---------------- convert: fp32 -> fp16 ----------------
DEVINL void cvt4(float4 v, __half* dst, int i) {
    uint2 u;
    u.x = pk2h(__float2half_rn(v.x), __float2half_rn(v.y));
    u.y = pk2h(__float2half_rn(v.z), __float2half_rn(v.w));
    reinterpret_cast<uint2*>(dst)[i] = u;
}

__global__ void convert_kernel(const float4* __restrict__ x,
                               const float4* __restrict__ wu,
                               const float4* __restrict__ wd) {
    const int X4  = M_TOK * K1 / 4;
    const int WU4 = N1 * K1 / 4;
    const int WD4 = N2 * K2 / 4;
    const int stride = gridDim.x * blockDim.x;
    const int t0 = blockIdx.x * blockDim.x + threadIdx.x;
    for (int i = t0; i < X4;  i += stride) cvt4(x[i],  g_x,  i);
    for (int i = t0; i < WU4; i += stride) cvt4(wu[i], g_wu, i);
    for (int i = t0; i < WD4; i += stride) cvt4(wd[i], g_wd, i);
}

// ---------------- tile loader (SW128 swizzle) ----------------
template <int ROWS>
DEVINL void load_tile(uint32_t sub, const __half* __restrict__ src,
                      int row0, int k0, int KDIM, int tid) {
    constexpr int ITERS = ROWS * 8 / NTHREADS;
#pragma unroll
    for (int j = 0; j < ITERS; j++) {
        const int idx = tid + j * NTHREADS;
        const int rr = idx >> 3;
        const int ss = idx & 7;
        const uint32_t off = (uint32_t)(rr * 128 + ss * 16);
        const uint32_t dst = sub + (off ^ ((off >> 3) & 0x70));
        cp16(dst, src + (size_t)(row0 + rr) * KDIM + (k0 + ss * 8));
    }
}

template <int TNL>
DEVINL void load_chunk(uint32_t sb, int k0, int tid,
                       const __half* A, const __half* B,
                       int m0, int n0, int KDIM) {
    load_tile<TM>(sb,           A, m0, k0, KDIM, tid);
    load_tile<TNL>(sb + A_TILE, B, n0, k0, KDIM, tid);
    cp_commit();
}

// ---------------- one K=16 step of the warp-tile MMA ----------------
template <int GN>
DEVINL void compute_ks(uint32_t sb, int ks, int lane, int wm, int wn,
                       float (&acc)[4][2 * GN][4]) {
    const uint32_t subA = sb;
    const uint32_t subB = sb + A_TILE;

    const int a_r0 = wm * 64 + (lane & 7) + ((lane >> 3) & 1) * 8;   // + mb*16
    const int a_k8 = (lane >> 4);
    const int b_r0 = wn * (GN * 16) + (lane & 7) + (lane >> 4) * 8;  // + g*16
    const int b_k8 = (lane >> 3) & 1;

    uint32_t a[4][4];
#pragma unroll
    for (int mb = 0; mb < 4; mb++) {
        const int r = a_r0 + mb * 16;
        const int kk = ks * 16 + a_k8 * 8;
        const uint32_t off = (uint32_t)(r * 128) + (((uint32_t)(kk * 2)) ^ (uint32_t)((r & 7) << 4));
        ldsm4(a[mb], subA + off);
    }
#pragma unroll
    for (int g = 0; g < GN; g++) {
        const int r = b_r0 + g * 16;
        const int kk = ks * 16 + b_k8 * 8;
        const uint32_t off = (uint32_t)(r * 128) + (((uint32_t)(kk * 2)) ^ (uint32_t)((r & 7) << 4));
        uint32_t b[4];
        ldsm4(b, subB + off);
#pragma unroll
        for (int h = 0; h < 2; h++)
#pragma unroll
            for (int mb = 0; mb < 4; mb++)
                mma16816(acc[mb][g * 2 + h], a[mb], b + 2 * h);
    }
}

// ---------------- GEMM body ----------------
// MODE 1: X * WupT, fused silu*mask -> h (fp16).  TN=128, PDL over convert.
// MODE 2: h * WdnT -> out fp32.                   TN=64,  PDL: B loads pre-sync.
template <int MODE>
__global__ void __launch_bounds__(NTHREADS, 2)
gemm_kernel(const float* __restrict__ mask, float* __restrict__ out) {
    constexpr int KDIM = (MODE == 1) ? K1 : K2;
    constexpr int NC = KDIM / KC;
    constexpr int TNL = (MODE == 1) ? 128 : 64;
    constexpr int GN = TNL / 32;                   // B 16-col groups per warp
    constexpr int B_TILE_L = TNL * KC * 2;
    constexpr int STAGE_L = A_TILE + B_TILE_L;
    const __half* A = (MODE == 1) ? g_x  : g_h;
    const __half* B = (MODE == 1) ? g_wu : g_wd;

    extern __shared__ __align__(1024) uint8_t smem_raw[];
    const uint32_t base = (smem_u32(smem_raw) + 1023u) & ~1023u;

    const int tid = threadIdx.x;
    const int lane = tid & 31;
    const int wid = tid >> 5;
    const int wm = wid >> 1;          // 0..1  (64-row half)
    const int wn = wid & 1;           // 0..1  (n half)
    const int m0 = blockIdx.y * TM;
    const int n0 = blockIdx.x * TNL;

    float acc[4][2 * GN][4];
#pragma unroll
    for (int i = 0; i < 4; i++)
#pragma unroll
        for (int j = 0; j < 2 * GN; j++)
#pragma unroll
            for (int q = 0; q < 4; q++) acc[i][j][q] = 0.f;

    // ---------------- prologue ----------------
    if (MODE == 2) {
        // PDL: B (g_wd) does not depend on GEMM1. Prefetch it before the
        // cross-kernel dependency sync; then A (g_h) after.
        load_tile<TNL>(base + A_TILE,           B, n0, 0,  KDIM, tid);
        load_tile<TNL>(base + STAGE_L + A_TILE, B, n0, KC, KDIM, tid);
        cudaGridDependencySynchronize();
        load_tile<TM>(base,           A, m0, 0,  KDIM, tid);
        cp_commit();                                // group0 = {B0, B1, A0}
        load_tile<TM>(base + STAGE_L, A, m0, KC, KDIM, tid);
        cp_commit();                                // group1 = {A1}
    } else {
        // PDL over convert: block launch/setup overlaps convert's tail; all
        // loads depend on convert output, so sync before the first cp.async.
        cudaGridDependencySynchronize();
        load_chunk<TNL>(base,           0,  tid, A, B, m0, n0, KDIM);
        load_chunk<TNL>(base + STAGE_L, KC, tid, A, B, m0, n0, KDIM);
    }

    for (int c = 0; c < NC; ++c) {
        if (c + 1 < NC) cp_wait<1>(); else cp_wait<0>();
        __syncthreads();   // chunk c resident; stage (c-1)%3 free

        const uint32_t sbc = base + (c % STAGES) * STAGE_L;

        // first K=16 step: tensor pipe busy immediately after the barrier
        compute_ks<GN>(sbc, 0, lane, wm, wn, acc);

        // issue next stage's loads in the MMA shadow
        if (c + 2 < NC)
            load_chunk<TNL>(base + ((c + 2) % STAGES) * STAGE_L, (c + 2) * KC,
                            tid, A, B, m0, n0, KDIM);

        // remaining K=16 steps
#pragma unroll
        for (int ks = 1; ks < KC / 16; ks++)
            compute_ks<GN>(sbc, ks, lane, wm, wn, acc);
    }

    // ---------------- epilogue ----------------
    const int mw0 = m0 + wm * 64;
    const int nw0 = n0 + wn * (GN * 16);
#pragma unroll
    for (int mb = 0; mb < 4; mb++) {
        const int r0 = mw0 + mb * 16 + (lane >> 2);
        if (MODE == 1) {
            const int e = nw0 >> 6;   // one expert per 64-wide warp n-tile (R=64)
            const float mk0 = mask[(size_t)r0 * NEXP + e];
            const float mk1 = mask[(size_t)(r0 + 8) * NEXP + e];
#pragma unroll
            for (int nb = 0; nb < 2 * GN; nb++) {
                const int col = nw0 + nb * 8 + (lane & 3) * 2;
                float v[4] = {acc[mb][nb][0], acc[mb][nb][1],
                              acc[mb][nb][2], acc[mb][nb][3]};
                float hv[4];
                hv[0] = v[0] * (1.f / (1.f + __expf(-v[0]))) * mk0;
                hv[1] = v[1] * (1.f / (1.f + __expf(-v[1]))) * mk0;
                hv[2] = v[2] * (1.f / (1.f + __expf(-v[2]))) * mk1;
                hv[3] = v[3] * (1.f / (1.f + __expf(-v[3]))) * mk1;
                *reinterpret_cast<uint32_t*>(g_h + (size_t)r0 * K2 + col) =
                    pk2h(__float2half_rn(hv[0]), __float2half_rn(hv[1]));
                *reinterpret_cast<uint32_t*>(g_h + (size_t)(r0 + 8) * K2 + col) =
                    pk2h(__float2half_rn(hv[2]), __float2half_rn(hv[3]));
            }
        } else {
#pragma unroll
            for (int nb = 0; nb < 2 * GN; nb++) {
                const int col = nw0 + nb * 8 + (lane & 3) * 2;
                *reinterpret_cast<float2*>(out + (size_t)r0 * N2 + col) =
                    make_float2(acc[mb][nb][0], acc[mb][nb][1]);
                *reinterpret_cast<float2*>(out + (size_t)(r0 + 8) * N2 + col) =
                    make_float2(acc[mb][nb][2], acc[mb][nb][3]);
            }
        }
    }

    if (MODE == 1) {
        // all of this block's h stores issued; let GEMM2 start launching
        cudaTriggerProgrammaticLaunchCompletion();
    }
}

// ---------------- launch ----------------
extern "C" void kernel_launch(void* const* d_in, const int* in_sizes, int n_in,
                              void* d_out, int out_size) {
    const float* x    = (const float*)d_in[0];   // [8192, 2048]
    const float* mask = (const float*)d_in[1];   // [8192, 64]
    const float* wu   = (const float*)d_in[2];   // [4096, 2048]
    const float* wd   = (const float*)d_in[3];   // [2048, 4096]
    float* out = (float*)d_out;

    constexpr int SMEM1 = STAGES * (A_TILE + 128 * KC * 2) + 1024;  // 97 KB
    constexpr int SMEM2 = STAGES * (A_TILE + 64  * KC * 2) + 1024;  // 73.5 KB

    cudaFuncSetAttribute(gemm_kernel<1>, cudaFuncAttributeMaxDynamicSharedMemorySize, SMEM1);
    cudaFuncSetAttribute(gemm_kernel<2>, cudaFuncAttributeMaxDynamicSharedMemorySize, SMEM2);

    convert_kernel<<<1024, 256>>>((const float4*)x, (const float4*)wu, (const float4*)wd);

    // GEMM1 with PDL over convert: launch/setup overlaps convert's tail.
    {
        cudaLaunchConfig_t cfg = {};
        cfg.gridDim = dim3(N1 / 128, M_TOK / TM);
        cfg.blockDim = dim3(NTHREADS, 1, 1);
        cfg.dynamicSmemBytes = SMEM1;
        cfg.stream = 0;
        cudaLaunchAttribute attrs[1];
        attrs[0].id = cudaLaunchAttributeProgrammaticStreamSerialization;
        attrs[0].val.programmaticStreamSerializationAllowed = 1;
        cfg.attrs = attrs;
        cfg.numAttrs = 1;
        cudaLaunchKernelEx(&cfg, gemm_kernel<1>, mask, (float*)nullptr);
    }

    // GEMM2 with PDL: overlaps its launch + B prefetch with GEMM1's tail wave.
    {
        cudaLaunchConfig_t cfg = {};
        cfg.gridDim = dim3(N2 / 64, M_TOK / TM);
        cfg.blockDim = dim3(NTHREADS, 1, 1);
        cfg.dynamicSmemBytes = SMEM2;
        cfg.stream = 0;
        cudaLaunchAttribute attrs[1];
        attrs[0].id = cudaLaunchAttributeProgrammaticStreamSerialization;
        attrs[0].val.programmaticStreamSerializationAllowed = 1;
        cfg.attrs = attrs;
        cfg.numAttrs = 1;
        cudaLaunchKernelEx(&cfg, gemm_kernel<2>, (const float*)nullptr, out);
    }
}